// round 2
// baseline (speedup 1.0000x reference)
#include <cuda_runtime.h>
#include <math.h>

// Problem constants (fixed shapes)
#define NN 50000
#define EE 800000
#define DIN 256
#define HH 128
#define RR 8
#define HEADS 8
#define DHH 16
#define OUTC 3

// ---------------- scratch (device globals; no allocation allowed) ----------
__device__ float g_S[(size_t)NN * RR * HH];     // per-(node,relation) aggregated features
__device__ float g_h1[(size_t)NN * HH];
__device__ float g_h2[(size_t)NN * HH];
__device__ float g_h3[(size_t)NN * HH];
__device__ float g_z[(size_t)NN * HH];
__device__ float g_deg[(size_t)NN * RR];        // degree -> invdeg in place
__device__ float g_asrc[(size_t)NN * HEADS];
__device__ float g_atgt[(size_t)NN * HEADS];
__device__ unsigned g_amax[(size_t)NN * HEADS];
__device__ float g_denom[(size_t)NN * HEADS];
__device__ float g_alpha[(size_t)EE * HEADS];
__device__ float g_outun[(size_t)NN * HH];

// ---------------- helpers ----------------
__device__ __forceinline__ void red4(float* p, float a, float b, float c, float d) {
    asm volatile("red.global.add.v4.f32 [%0], {%1,%2,%3,%4};"
                 :: "l"(p), "f"(a), "f"(b), "f"(c), "f"(d) : "memory");
}

__device__ __forceinline__ unsigned enc_f(float f) {
    unsigned u = __float_as_uint(f);
    return (u & 0x80000000u) ? ~u : (u | 0x80000000u);
}
__device__ __forceinline__ float dec_f(unsigned k) {
    unsigned u = (k & 0x80000000u) ? (k & 0x7FFFFFFFu) : ~k;
    return __uint_as_float(u);
}
#define ENC_NEG_INF 0x007FFFFFu   // enc(-inf)

// ---------------- fill kernels ----------------
__global__ void fill_f4(float4* p, int n4, float v) {
    float4 q = make_float4(v, v, v, v);
    for (int i = blockIdx.x * blockDim.x + threadIdx.x; i < n4; i += gridDim.x * blockDim.x)
        p[i] = q;
}
__global__ void fill_u4(uint4* p, int n4, unsigned v) {
    uint4 q = make_uint4(v, v, v, v);
    for (int i = blockIdx.x * blockDim.x + threadIdx.x; i < n4; i += gridDim.x * blockDim.x)
        p[i] = q;
}

// ---------------- GEMM: C[M,128] = A @ B (+ A2 @ B2) + bias, optional relu ---
// MODE 0: plain, A[M,K] row-major, B[K,128]
// MODE 1: RGCN,  A = S[M,1024] scaled by invdeg per 128-block, B = W[1024,128],
//                A2 = h[M,128], B2 = root[128,128], Ksplit=1024, K=1152
template<int MODE, bool RELU>
__global__ __launch_bounds__(256) void gemm128(
    const float* __restrict__ A, const float* __restrict__ B,
    const float* __restrict__ A2, const float* __restrict__ B2,
    const float* __restrict__ invdeg, const float* __restrict__ bias,
    float* __restrict__ C, int M, int K, int Ksplit)
{
    constexpr int BM = 128, BN = 128, BK = 16, TM = 8, TN = 8;
    __shared__ float As[BK][BM + 4];
    __shared__ float Bs[BK][BN];

    const int tid = threadIdx.x;
    const int tx = tid & 15;
    const int ty = tid >> 4;
    const int bm = blockIdx.x * BM;

    const int ar = tid >> 2;         // 0..63 (row within tile, +64 for second)
    const int ac = (tid & 3) << 2;   // 0,4,8,12 (k offset within tile)
    const int br = tid >> 5;         // 0..7
    const int bc = (tid & 31) << 2;  // 0..124

    float acc[TM][TN];
#pragma unroll
    for (int i = 0; i < TM; i++)
#pragma unroll
        for (int j = 0; j < TN; j++) acc[i][j] = 0.0f;

    for (int k0 = 0; k0 < K; k0 += BK) {
        // --- load A tile (transposed into As[k][m]) ---
#pragma unroll
        for (int i = 0; i < 2; i++) {
            int row = bm + ar + i * 64;
            int kk = k0 + ac;
            float4 v = make_float4(0.f, 0.f, 0.f, 0.f);
            if (row < M) {
                if (MODE == 1) {
                    if (kk < Ksplit) {
                        v = *(const float4*)(A + (size_t)row * Ksplit + kk);
                        float sc = invdeg[row * RR + (kk >> 7)];
                        v.x *= sc; v.y *= sc; v.z *= sc; v.w *= sc;
                    } else {
                        v = *(const float4*)(A2 + (size_t)row * HH + (kk - Ksplit));
                    }
                } else {
                    v = *(const float4*)(A + (size_t)row * K + kk);
                }
            }
            As[ac + 0][ar + i * 64] = v.x;
            As[ac + 1][ar + i * 64] = v.y;
            As[ac + 2][ar + i * 64] = v.z;
            As[ac + 3][ar + i * 64] = v.w;
        }
        // --- load B tile ---
#pragma unroll
        for (int i = 0; i < 2; i++) {
            int kk = k0 + br + i * 8;
            const float* Bp;
            if (MODE == 1 && kk >= Ksplit)
                Bp = B2 + (size_t)(kk - Ksplit) * BN + bc;
            else
                Bp = B + (size_t)kk * BN + bc;
            *(float4*)&Bs[br + i * 8][bc] = *(const float4*)Bp;
        }
        __syncthreads();
#pragma unroll
        for (int kk = 0; kk < BK; kk++) {
            float a[TM], b[TN];
#pragma unroll
            for (int i = 0; i < TM; i++) a[i] = As[kk][ty * TM + i];
#pragma unroll
            for (int j = 0; j < TN; j++) b[j] = Bs[kk][tx * TN + j];
#pragma unroll
            for (int i = 0; i < TM; i++)
#pragma unroll
                for (int j = 0; j < TN; j++) acc[i][j] += a[i] * b[j];
        }
        __syncthreads();
    }

#pragma unroll
    for (int i = 0; i < TM; i++) {
        int row = bm + ty * TM + i;
        if (row >= M) continue;
#pragma unroll
        for (int j = 0; j < TN; j += 4) {
            int col = tx * TN + j;
            float4 v;
            v.x = acc[i][j + 0] + (bias ? bias[col + 0] : 0.f);
            v.y = acc[i][j + 1] + (bias ? bias[col + 1] : 0.f);
            v.z = acc[i][j + 2] + (bias ? bias[col + 2] : 0.f);
            v.w = acc[i][j + 3] + (bias ? bias[col + 3] : 0.f);
            if (RELU) {
                v.x = fmaxf(v.x, 0.f); v.y = fmaxf(v.y, 0.f);
                v.z = fmaxf(v.z, 0.f); v.w = fmaxf(v.w, 0.f);
            }
            *(float4*)(C + (size_t)row * HH + col) = v;
        }
    }
}

// ---------------- RGCN scatter: warp per edge ----------------
__global__ void rgcn_scatter(const int* __restrict__ src, const int* __restrict__ tgt,
                             const int* __restrict__ et, const float* __restrict__ h,
                             float* __restrict__ S, float* __restrict__ deg, int E)
{
    int w = (blockIdx.x * blockDim.x + threadIdx.x) >> 5;
    int lane = threadIdx.x & 31;
    if (w >= E) return;
    int s = src[w], t = tgt[w], r = et[w];
    float4 v = ((const float4*)(h + (size_t)s * HH))[lane];
    float* dst = S + (size_t)t * (RR * HH) + r * HH + lane * 4;
    red4(dst, v.x, v.y, v.z, v.w);
    if (lane == 0) atomicAdd(deg + t * RR + r, 1.0f);
}

__global__ void make_invdeg(float* deg, int n) {
    int i = blockIdx.x * blockDim.x + threadIdx.x;
    if (i < n) deg[i] = 1.0f / fmaxf(deg[i], 1.0f);
}

// ---------------- GAT ----------------
__global__ void att_node(const float* __restrict__ z, const float* __restrict__ att,
                         float* __restrict__ asrc, float* __restrict__ atgt, int n)
{
    int i = blockIdx.x * blockDim.x + threadIdx.x;
    if (i >= n * HEADS) return;
    int node = i >> 3, hd = i & 7;
    const float* zp = z + (size_t)node * HH + hd * DHH;
    const float* al = att + hd * (2 * DHH);
    float sa = 0.f, sb = 0.f;
#pragma unroll
    for (int d = 0; d < DHH; d++) {
        float zv = zp[d];
        sa += zv * al[d];
        sb += zv * al[DHH + d];
    }
    asrc[i] = sa;
    atgt[i] = sb;
}

__global__ void gat_pass1(const int* __restrict__ src, const int* __restrict__ tgt,
                          const float* __restrict__ asrc, const float* __restrict__ atgt,
                          float* __restrict__ alpha, unsigned* __restrict__ amax, int E)
{
    int e = blockIdx.x * blockDim.x + threadIdx.x;
    if (e >= E) return;
    int s = src[e], t = tgt[e];
    float4 s0 = ((const float4*)(asrc + (size_t)s * HEADS))[0];
    float4 s1 = ((const float4*)(asrc + (size_t)s * HEADS))[1];
    float4 t0 = ((const float4*)(atgt + (size_t)t * HEADS))[0];
    float4 t1 = ((const float4*)(atgt + (size_t)t * HEADS))[1];
    float a[8] = { s0.x + t0.x, s0.y + t0.y, s0.z + t0.z, s0.w + t0.w,
                   s1.x + t1.x, s1.y + t1.y, s1.z + t1.z, s1.w + t1.w };
#pragma unroll
    for (int hd = 0; hd < 8; hd++) a[hd] = a[hd] > 0.f ? a[hd] : 0.2f * a[hd];
    ((float4*)(alpha + (size_t)e * HEADS))[0] = make_float4(a[0], a[1], a[2], a[3]);
    ((float4*)(alpha + (size_t)e * HEADS))[1] = make_float4(a[4], a[5], a[6], a[7]);
#pragma unroll
    for (int hd = 0; hd < 8; hd++) atomicMax(amax + t * HEADS + hd, enc_f(a[hd]));
}

__global__ void gat_pass2(const int* __restrict__ src, const int* __restrict__ tgt,
                          const float* __restrict__ alpha, const unsigned* __restrict__ amax,
                          const float* __restrict__ z, float* __restrict__ denom,
                          float* __restrict__ outun, int E)
{
    int w = (blockIdx.x * blockDim.x + threadIdx.x) >> 5;
    int lane = threadIdx.x & 31;
    if (w >= E) return;
    int s = src[w], t = tgt[w];
    int head = lane >> 2;
    float al = alpha[(size_t)w * HEADS + head];
    float am = dec_f(amax[t * HEADS + head]);
    float ex = __expf(al - am);
    if ((lane & 3) == 0) atomicAdd(denom + t * HEADS + head, ex);
    float4 zv = ((const float4*)(z + (size_t)s * HH))[lane];
    red4(outun + (size_t)t * HH + lane * 4, zv.x * ex, zv.y * ex, zv.z * ex, zv.w * ex);
}

// finalize: gat-normalize + bg, then 128x3 projection, log_softmax. Warp per node.
__global__ void finalize(const float* __restrict__ outun, const float* __restrict__ denom,
                         const float* __restrict__ bg, const float* __restrict__ Wf,
                         const float* __restrict__ bf, float* __restrict__ out, int n)
{
    int w = (blockIdx.x * blockDim.x + threadIdx.x) >> 5;
    int lane = threadIdx.x & 31;
    if (w >= n) return;
    float4 g = ((const float4*)(outun + (size_t)w * HH))[lane];
    int head = lane >> 2;
    float dn = denom[w * HEADS + head];
    float inv = 1.0f / fmaxf(dn, 1e-16f);
    float4 bgv = ((const float4*)bg)[lane];
    float gv[4] = { g.x * inv + bgv.x, g.y * inv + bgv.y,
                    g.z * inv + bgv.z, g.w * inv + bgv.w };
    float a0 = 0.f, a1 = 0.f, a2 = 0.f;
    int j0 = lane * 4;
#pragma unroll
    for (int c = 0; c < 4; c++) {
        int j = j0 + c;
        a0 += gv[c] * Wf[j * OUTC + 0];
        a1 += gv[c] * Wf[j * OUTC + 1];
        a2 += gv[c] * Wf[j * OUTC + 2];
    }
#pragma unroll
    for (int off = 16; off > 0; off >>= 1) {
        a0 += __shfl_xor_sync(0xFFFFFFFFu, a0, off);
        a1 += __shfl_xor_sync(0xFFFFFFFFu, a1, off);
        a2 += __shfl_xor_sync(0xFFFFFFFFu, a2, off);
    }
    if (lane == 0) {
        float l0 = a0 + bf[0], l1 = a1 + bf[1], l2 = a2 + bf[2];
        float m = fmaxf(l0, fmaxf(l1, l2));
        float lse = m + logf(expf(l0 - m) + expf(l1 - m) + expf(l2 - m));
        out[(size_t)w * OUTC + 0] = l0 - lse;
        out[(size_t)w * OUTC + 1] = l1 - lse;
        out[(size_t)w * OUTC + 2] = l2 - lse;
    }
}

// ---------------- launch ----------------
extern "C" void kernel_launch(void* const* d_in, const int* in_sizes, int n_in,
                              void* d_out, int out_size)
{
    const float* x     = (const float*)d_in[0];
    const int*   ei    = (const int*)d_in[1];
    const int*   etype = (const int*)d_in[2];
    const float* Wp    = (const float*)d_in[3];
    const float* bp    = (const float*)d_in[4];
    const float* W1    = (const float*)d_in[5];
    const float* root1 = (const float*)d_in[6];
    const float* b1    = (const float*)d_in[7];
    const float* W2    = (const float*)d_in[8];
    const float* root2 = (const float*)d_in[9];
    const float* b2    = (const float*)d_in[10];
    const float* Wg    = (const float*)d_in[11];
    const float* att   = (const float*)d_in[12];
    const float* bg    = (const float*)d_in[13];
    const float* Wf    = (const float*)d_in[14];
    const float* bf    = (const float*)d_in[15];
    float* out = (float*)d_out;

    const int* src = ei;
    const int* tgt = ei + EE;

    float *S, *h1, *h2, *h3, *z, *deg, *asrc, *atgt, *denom, *alpha, *outun;
    unsigned* amax;
    cudaGetSymbolAddress((void**)&S, g_S);
    cudaGetSymbolAddress((void**)&h1, g_h1);
    cudaGetSymbolAddress((void**)&h2, g_h2);
    cudaGetSymbolAddress((void**)&h3, g_h3);
    cudaGetSymbolAddress((void**)&z, g_z);
    cudaGetSymbolAddress((void**)&deg, g_deg);
    cudaGetSymbolAddress((void**)&asrc, g_asrc);
    cudaGetSymbolAddress((void**)&atgt, g_atgt);
    cudaGetSymbolAddress((void**)&denom, g_denom);
    cudaGetSymbolAddress((void**)&alpha, g_alpha);
    cudaGetSymbolAddress((void**)&outun, g_outun);
    cudaGetSymbolAddress((void**)&amax, g_amax);

    const int gemmGrid = (NN + 127) / 128;   // 391
    const int scatGrid = (EE + 7) / 8;       // warp/edge, 8 warps/block
    const int fillGrid = 4096;

    // ---- projection: h1 = x @ Wp + bp
    gemm128<0, false><<<gemmGrid, 256>>>(x, Wp, nullptr, nullptr, nullptr, bp, h1, NN, DIN, DIN);

    // ---- RGCN layer 1 -> h2
    fill_f4<<<fillGrid, 256>>>((float4*)S, NN * RR * HH / 4, 0.f);
    fill_f4<<<64, 256>>>((float4*)deg, NN * RR / 4, 0.f);
    rgcn_scatter<<<scatGrid, 256>>>(src, tgt, etype, h1, S, deg, EE);
    make_invdeg<<<(NN * RR + 255) / 256, 256>>>(deg, NN * RR);
    gemm128<1, true><<<gemmGrid, 256>>>(S, W1, h1, root1, deg, b1, h2, NN, RR * HH + HH, RR * HH);

    // ---- RGCN layer 2 -> h3
    fill_f4<<<fillGrid, 256>>>((float4*)S, NN * RR * HH / 4, 0.f);
    fill_f4<<<64, 256>>>((float4*)deg, NN * RR / 4, 0.f);
    rgcn_scatter<<<scatGrid, 256>>>(src, tgt, etype, h2, S, deg, EE);
    make_invdeg<<<(NN * RR + 255) / 256, 256>>>(deg, NN * RR);
    gemm128<1, true><<<gemmGrid, 256>>>(S, W2, h2, root2, deg, b2, h3, NN, RR * HH + HH, RR * HH);

    // ---- GAT
    gemm128<0, false><<<gemmGrid, 256>>>(h3, Wg, nullptr, nullptr, nullptr, nullptr, z, NN, HH, HH);
    att_node<<<(NN * HEADS + 255) / 256, 256>>>(z, att, asrc, atgt, NN);
    fill_u4<<<64, 256>>>((uint4*)amax, NN * HEADS / 4, ENC_NEG_INF);
    fill_f4<<<64, 256>>>((float4*)denom, NN * HEADS / 4, 0.f);
    fill_f4<<<512, 256>>>((float4*)outun, NN * HH / 4, 0.f);
    gat_pass1<<<(EE + 255) / 256, 256>>>(src, tgt, asrc, atgt, alpha, amax, EE);
    gat_pass2<<<scatGrid, 256>>>(src, tgt, alpha, amax, z, denom, outun, EE);

    // ---- finalize: normalize + bg + Wf/bf + log_softmax
    finalize<<<(NN + 7) / 8, 256>>>(outun, denom, bg, Wf, bf, out, NN);
}

// round 4
// speedup vs baseline: 1.6728x; 1.6728x over previous
#include <cuda_runtime.h>
#include <cuda_bf16.h>
#include <math.h>
#include <stdint.h>

// Problem constants (fixed shapes)
#define NN 50000
#define EE 800000
#define DIN 256
#define HH 128
#define RR 8
#define HEADS 8
#define DHH 16
#define OUTC 3

// ---------------- scratch (device globals; no allocation allowed) ----------
__device__ float g_S[(size_t)NN * RR * HH];
__device__ float g_h1[(size_t)NN * HH];
__device__ float g_h2[(size_t)NN * HH];
__device__ float g_h3[(size_t)NN * HH];
__device__ float g_z[(size_t)NN * HH];
__device__ float g_deg[(size_t)NN * RR];
__device__ float g_asrc[(size_t)NN * HEADS];
__device__ float g_atgt[(size_t)NN * HEADS];
__device__ unsigned g_amax[(size_t)NN * HEADS];
__device__ float g_denom[(size_t)NN * HEADS];
__device__ float g_alpha[(size_t)EE * HEADS];
__device__ float g_outun[(size_t)NN * HH];

// ---------------- helpers ----------------
__device__ __forceinline__ void red4(float* p, float a, float b, float c, float d) {
    asm volatile("red.global.add.v4.f32 [%0], {%1,%2,%3,%4};"
                 :: "l"(p), "f"(a), "f"(b), "f"(c), "f"(d) : "memory");
}
__device__ __forceinline__ unsigned enc_f(float f) {
    unsigned u = __float_as_uint(f);
    return (u & 0x80000000u) ? ~u : (u | 0x80000000u);
}
__device__ __forceinline__ float dec_f(unsigned k) {
    unsigned u = (k & 0x80000000u) ? (k & 0x7FFFFFFFu) : ~k;
    return __uint_as_float(u);
}
#define ENC_NEG_INF 0x007FFFFFu

// split float pair (x = k even, y = k odd) into packed bf16x2 hi + lo
__device__ __forceinline__ void split2(float x, float y, uint32_t& hp, uint32_t& lp) {
    __nv_bfloat16 xh = __float2bfloat16(x);
    __nv_bfloat16 yh = __float2bfloat16(y);
    float xr = x - __bfloat162float(xh);
    float yr = y - __bfloat162float(yh);
    __nv_bfloat16 xl = __float2bfloat16(xr);
    __nv_bfloat16 yl = __float2bfloat16(yr);
    hp = ((uint32_t)__bfloat16_as_ushort(yh) << 16) | (uint32_t)__bfloat16_as_ushort(xh);
    lp = ((uint32_t)__bfloat16_as_ushort(yl) << 16) | (uint32_t)__bfloat16_as_ushort(xl);
}

__device__ __forceinline__ void mma_bf16(float& c0, float& c1, float& c2, float& c3,
                                         uint32_t a0, uint32_t a1, uint32_t a2, uint32_t a3,
                                         uint32_t b0, uint32_t b1) {
    asm volatile("mma.sync.aligned.m16n8k16.row.col.f32.bf16.bf16.f32 "
                 "{%0,%1,%2,%3}, {%4,%5,%6,%7}, {%8,%9}, {%0,%1,%2,%3};"
                 : "+f"(c0), "+f"(c1), "+f"(c2), "+f"(c3)
                 : "r"(a0), "r"(a1), "r"(a2), "r"(a3), "r"(b0), "r"(b1));
}

// ---------------- fill kernels ----------------
__global__ void fill_f4(float4* p, int n4, float v) {
    float4 q = make_float4(v, v, v, v);
    for (int i = blockIdx.x * blockDim.x + threadIdx.x; i < n4; i += gridDim.x * blockDim.x)
        p[i] = q;
}
__global__ void fill_u4(uint4* p, int n4, unsigned v) {
    uint4 q = make_uint4(v, v, v, v);
    for (int i = blockIdx.x * blockDim.x + threadIdx.x; i < n4; i += gridDim.x * blockDim.x)
        p[i] = q;
}

// -------- bf16x3 tensor-core GEMM: C[M,128] = A@B (+A2@B2) + bias ----------
// fp32-accurate via A=Ah+Al, B=Bh+Bl (bf16 splits); C = AhBh + AhBl + AlBh.
// MODE 0: plain, A[M,K] row-major, B[K,128]
// MODE 1: RGCN,  A = S[M,1024] scaled by invdeg per 128-col block, B = W[1024,128],
//                A2 = h[M,128], B2 = root[128,128], Ksplit=1024, K=1152
// Block 256 thr = 8 warps (4 in M x 2 in N). BM=BN=128, BK=16.
// Warp tile 32x64 via m16n8k16: 2 m-tiles x 8 n-tiles x 3 MMAs.
template<int MODE, bool RELU>
__global__ __launch_bounds__(256) void gemm_bf16x3(
    const float* __restrict__ A, const float* __restrict__ B,
    const float* __restrict__ A2, const float* __restrict__ B2,
    const float* __restrict__ invdeg, const float* __restrict__ bias,
    float* __restrict__ C, int M, int K, int Ksplit)
{
    constexpr int LDSW = 136;  // word stride: bank = (8*kp + idx) % 32, bijective
    __shared__ uint32_t As_h[8][LDSW], As_l[8][LDSW];   // [kpair][row]
    __shared__ uint32_t Bs_h[8][LDSW], Bs_l[8][LDSW];   // [kpair][col]

    const int tid = threadIdx.x;
    const int lane = tid & 31;
    const int warp = tid >> 5;
    const int warp_m = warp & 3;   // 32-row slab
    const int warp_n = warp >> 2;  // 64-col slab
    const int bm = blockIdx.x * 128;

    // A loader: row = tid&127, k offset 0 or 8 (8 consecutive floats -> 4 kpairs)
    const int a_row = tid & 127;
    const int a_k8 = (tid >> 7) << 3;
    // B loader: kpair = tid>>5 (0..7), col4 = (tid&31)*4
    const int b_kp = tid >> 5;
    const int b_c4 = (tid & 31) << 2;

    const int row_g = bm + a_row;
    const bool row_ok = (row_g < M);

    const int tig = lane & 3;
    const int gid = lane >> 2;

    float c[2][8][4];
#pragma unroll
    for (int i = 0; i < 2; i++)
#pragma unroll
        for (int j = 0; j < 8; j++)
#pragma unroll
            for (int q = 0; q < 4; q++) c[i][j][q] = 0.0f;

    for (int k0 = 0; k0 < K; k0 += 16) {
        // ---- load + split A tile ----
        {
            int kk = k0 + a_k8;
            float v[8] = {0.f, 0.f, 0.f, 0.f, 0.f, 0.f, 0.f, 0.f};
            if (row_ok) {
                float4 v0, v1;
                if (MODE == 1) {
                    if (kk < Ksplit) {
                        const float* p = A + (size_t)row_g * Ksplit + kk;
                        v0 = *(const float4*)p;
                        v1 = *(const float4*)(p + 4);
                        float sc = invdeg[row_g * RR + (kk >> 7)];
                        v0.x *= sc; v0.y *= sc; v0.z *= sc; v0.w *= sc;
                        v1.x *= sc; v1.y *= sc; v1.z *= sc; v1.w *= sc;
                    } else {
                        const float* p = A2 + (size_t)row_g * HH + (kk - Ksplit);
                        v0 = *(const float4*)p;
                        v1 = *(const float4*)(p + 4);
                    }
                } else {
                    const float* p = A + (size_t)row_g * K + kk;
                    v0 = *(const float4*)p;
                    v1 = *(const float4*)(p + 4);
                }
                v[0] = v0.x; v[1] = v0.y; v[2] = v0.z; v[3] = v0.w;
                v[4] = v1.x; v[5] = v1.y; v[6] = v1.z; v[7] = v1.w;
            }
            int kp0 = a_k8 >> 1;
#pragma unroll
            for (int i = 0; i < 4; i++) {
                uint32_t hp, lp;
                split2(v[2 * i], v[2 * i + 1], hp, lp);
                As_h[kp0 + i][a_row] = hp;
                As_l[kp0 + i][a_row] = lp;
            }
        }
        // ---- load + split B tile ----
        {
            int kr0 = k0 + 2 * b_kp;
            int kr1 = kr0 + 1;
            const float* p0 = (MODE == 1 && kr0 >= Ksplit)
                ? (B2 + (size_t)(kr0 - Ksplit) * 128 + b_c4)
                : (B + (size_t)kr0 * 128 + b_c4);
            const float* p1 = (MODE == 1 && kr1 >= Ksplit)
                ? (B2 + (size_t)(kr1 - Ksplit) * 128 + b_c4)
                : (B + (size_t)kr1 * 128 + b_c4);
            float4 r0 = *(const float4*)p0;
            float4 r1 = *(const float4*)p1;
            uint32_t hp[4], lp[4];
            split2(r0.x, r1.x, hp[0], lp[0]);
            split2(r0.y, r1.y, hp[1], lp[1]);
            split2(r0.z, r1.z, hp[2], lp[2]);
            split2(r0.w, r1.w, hp[3], lp[3]);
            *(uint4*)&Bs_h[b_kp][b_c4] = make_uint4(hp[0], hp[1], hp[2], hp[3]);
            *(uint4*)&Bs_l[b_kp][b_c4] = make_uint4(lp[0], lp[1], lp[2], lp[3]);
        }
        __syncthreads();

        // ---- fragments ----
        uint32_t ah[2][4], al[2][4];
#pragma unroll
        for (int mt = 0; mt < 2; mt++) {
            int r = warp_m * 32 + mt * 16 + gid;
            ah[mt][0] = As_h[tig][r];     ah[mt][1] = As_h[tig][r + 8];
            ah[mt][2] = As_h[tig + 4][r]; ah[mt][3] = As_h[tig + 4][r + 8];
            al[mt][0] = As_l[tig][r];     al[mt][1] = As_l[tig][r + 8];
            al[mt][2] = As_l[tig + 4][r]; al[mt][3] = As_l[tig + 4][r + 8];
        }
        uint32_t bh[8][2], bl[8][2];
#pragma unroll
        for (int nt = 0; nt < 8; nt++) {
            int cc = warp_n * 64 + nt * 8 + gid;
            bh[nt][0] = Bs_h[tig][cc]; bh[nt][1] = Bs_h[tig + 4][cc];
            bl[nt][0] = Bs_l[tig][cc]; bl[nt][1] = Bs_l[tig + 4][cc];
        }
#pragma unroll
        for (int mt = 0; mt < 2; mt++)
#pragma unroll
            for (int nt = 0; nt < 8; nt++) {
                mma_bf16(c[mt][nt][0], c[mt][nt][1], c[mt][nt][2], c[mt][nt][3],
                         ah[mt][0], ah[mt][1], ah[mt][2], ah[mt][3],
                         bh[nt][0], bh[nt][1]);
                mma_bf16(c[mt][nt][0], c[mt][nt][1], c[mt][nt][2], c[mt][nt][3],
                         ah[mt][0], ah[mt][1], ah[mt][2], ah[mt][3],
                         bl[nt][0], bl[nt][1]);
                mma_bf16(c[mt][nt][0], c[mt][nt][1], c[mt][nt][2], c[mt][nt][3],
                         al[mt][0], al[mt][1], al[mt][2], al[mt][3],
                         bh[nt][0], bh[nt][1]);
            }
        __syncthreads();
    }

    // ---- epilogue ----
    const int er0 = bm + warp_m * 32 + gid;
    const int ec0 = warp_n * 64 + (tig << 1);
#pragma unroll
    for (int mt = 0; mt < 2; mt++) {
#pragma unroll
        for (int half = 0; half < 2; half++) {
            int row = er0 + mt * 16 + half * 8;
            if (row >= M) continue;
#pragma unroll
            for (int nt = 0; nt < 8; nt++) {
                int col = ec0 + nt * 8;
                float v0 = c[mt][nt][half * 2 + 0];
                float v1 = c[mt][nt][half * 2 + 1];
                if (bias) { v0 += bias[col]; v1 += bias[col + 1]; }
                if (RELU) { v0 = fmaxf(v0, 0.f); v1 = fmaxf(v1, 0.f); }
                *(float2*)(C + (size_t)row * HH + col) = make_float2(v0, v1);
            }
        }
    }
}

// ---------------- RGCN scatter: warp per edge ----------------
__global__ void rgcn_scatter(const int* __restrict__ src, const int* __restrict__ tgt,
                             const int* __restrict__ et, const float* __restrict__ h,
                             float* __restrict__ S, float* __restrict__ deg, int E)
{
    int w = (blockIdx.x * blockDim.x + threadIdx.x) >> 5;
    int lane = threadIdx.x & 31;
    if (w >= E) return;
    int s = src[w], t = tgt[w], r = et[w];
    float4 v = ((const float4*)(h + (size_t)s * HH))[lane];
    float* dst = S + (size_t)t * (RR * HH) + r * HH + lane * 4;
    red4(dst, v.x, v.y, v.z, v.w);
    if (lane == 0) atomicAdd(deg + t * RR + r, 1.0f);
}

__global__ void make_invdeg(float* deg, int n) {
    int i = blockIdx.x * blockDim.x + threadIdx.x;
    if (i < n) deg[i] = 1.0f / fmaxf(deg[i], 1.0f);
}

// ---------------- GAT ----------------
__global__ void att_node(const float* __restrict__ z, const float* __restrict__ att,
                         float* __restrict__ asrc, float* __restrict__ atgt, int n)
{
    int i = blockIdx.x * blockDim.x + threadIdx.x;
    if (i >= n * HEADS) return;
    int node = i >> 3, hd = i & 7;
    const float* zp = z + (size_t)node * HH + hd * DHH;
    const float* al = att + hd * (2 * DHH);
    float sa = 0.f, sb = 0.f;
#pragma unroll
    for (int d = 0; d < DHH; d++) {
        float zv = zp[d];
        sa += zv * al[d];
        sb += zv * al[DHH + d];
    }
    asrc[i] = sa;
    atgt[i] = sb;
}

__global__ void gat_pass1(const int* __restrict__ src, const int* __restrict__ tgt,
                          const float* __restrict__ asrc, const float* __restrict__ atgt,
                          float* __restrict__ alpha, unsigned* __restrict__ amax, int E)
{
    int e = blockIdx.x * blockDim.x + threadIdx.x;
    if (e >= E) return;
    int s = src[e], t = tgt[e];
    float4 s0 = ((const float4*)(asrc + (size_t)s * HEADS))[0];
    float4 s1 = ((const float4*)(asrc + (size_t)s * HEADS))[1];
    float4 t0 = ((const float4*)(atgt + (size_t)t * HEADS))[0];
    float4 t1 = ((const float4*)(atgt + (size_t)t * HEADS))[1];
    float a[8] = { s0.x + t0.x, s0.y + t0.y, s0.z + t0.z, s0.w + t0.w,
                   s1.x + t1.x, s1.y + t1.y, s1.z + t1.z, s1.w + t1.w };
#pragma unroll
    for (int hd = 0; hd < 8; hd++) a[hd] = a[hd] > 0.f ? a[hd] : 0.2f * a[hd];
    ((float4*)(alpha + (size_t)e * HEADS))[0] = make_float4(a[0], a[1], a[2], a[3]);
    ((float4*)(alpha + (size_t)e * HEADS))[1] = make_float4(a[4], a[5], a[6], a[7]);
#pragma unroll
    for (int hd = 0; hd < 8; hd++) atomicMax(amax + t * HEADS + hd, enc_f(a[hd]));
}

__global__ void gat_pass2(const int* __restrict__ src, const int* __restrict__ tgt,
                          const float* __restrict__ alpha, const unsigned* __restrict__ amax,
                          const float* __restrict__ z, float* __restrict__ denom,
                          float* __restrict__ outun, int E)
{
    int w = (blockIdx.x * blockDim.x + threadIdx.x) >> 5;
    int lane = threadIdx.x & 31;
    if (w >= E) return;
    int s = src[w], t = tgt[w];
    int head = lane >> 2;
    float al = alpha[(size_t)w * HEADS + head];
    float am = dec_f(amax[t * HEADS + head]);
    float ex = __expf(al - am);
    if ((lane & 3) == 0) atomicAdd(denom + t * HEADS + head, ex);
    float4 zv = ((const float4*)(z + (size_t)s * HH))[lane];
    red4(outun + (size_t)t * HH + lane * 4, zv.x * ex, zv.y * ex, zv.z * ex, zv.w * ex);
}

// finalize: gat-normalize + bg, then 128x3 projection, log_softmax. Warp per node.
__global__ void finalize(const float* __restrict__ outun, const float* __restrict__ denom,
                         const float* __restrict__ bg, const float* __restrict__ Wf,
                         const float* __restrict__ bf, float* __restrict__ out, int n)
{
    int w = (blockIdx.x * blockDim.x + threadIdx.x) >> 5;
    int lane = threadIdx.x & 31;
    if (w >= n) return;
    float4 g = ((const float4*)(outun + (size_t)w * HH))[lane];
    int head = lane >> 2;
    float dn = denom[w * HEADS + head];
    float inv = 1.0f / fmaxf(dn, 1e-16f);
    float4 bgv = ((const float4*)bg)[lane];
    float gv[4] = { g.x * inv + bgv.x, g.y * inv + bgv.y,
                    g.z * inv + bgv.z, g.w * inv + bgv.w };
    float a0 = 0.f, a1 = 0.f, a2 = 0.f;
    int j0 = lane * 4;
#pragma unroll
    for (int c = 0; c < 4; c++) {
        int j = j0 + c;
        a0 += gv[c] * Wf[j * OUTC + 0];
        a1 += gv[c] * Wf[j * OUTC + 1];
        a2 += gv[c] * Wf[j * OUTC + 2];
    }
#pragma unroll
    for (int off = 16; off > 0; off >>= 1) {
        a0 += __shfl_xor_sync(0xFFFFFFFFu, a0, off);
        a1 += __shfl_xor_sync(0xFFFFFFFFu, a1, off);
        a2 += __shfl_xor_sync(0xFFFFFFFFu, a2, off);
    }
    if (lane == 0) {
        float l0 = a0 + bf[0], l1 = a1 + bf[1], l2 = a2 + bf[2];
        float m = fmaxf(l0, fmaxf(l1, l2));
        float lse = m + logf(expf(l0 - m) + expf(l1 - m) + expf(l2 - m));
        out[(size_t)w * OUTC + 0] = l0 - lse;
        out[(size_t)w * OUTC + 1] = l1 - lse;
        out[(size_t)w * OUTC + 2] = l2 - lse;
    }
}

// ---------------- launch ----------------
extern "C" void kernel_launch(void* const* d_in, const int* in_sizes, int n_in,
                              void* d_out, int out_size)
{
    const float* x     = (const float*)d_in[0];
    const int*   ei    = (const int*)d_in[1];
    const int*   etype = (const int*)d_in[2];
    const float* Wp    = (const float*)d_in[3];
    const float* bp    = (const float*)d_in[4];
    const float* W1    = (const float*)d_in[5];
    const float* root1 = (const float*)d_in[6];
    const float* b1    = (const float*)d_in[7];
    const float* W2    = (const float*)d_in[8];
    const float* root2 = (const float*)d_in[9];
    const float* b2    = (const float*)d_in[10];
    const float* Wg    = (const float*)d_in[11];
    const float* att   = (const float*)d_in[12];
    const float* bg    = (const float*)d_in[13];
    const float* Wf    = (const float*)d_in[14];
    const float* bf    = (const float*)d_in[15];
    float* out = (float*)d_out;

    const int* src = ei;
    const int* tgt = ei + EE;

    float *S, *h1, *h2, *h3, *z, *deg, *asrc, *atgt, *denom, *alpha, *outun;
    unsigned* amax;
    cudaGetSymbolAddress((void**)&S, g_S);
    cudaGetSymbolAddress((void**)&h1, g_h1);
    cudaGetSymbolAddress((void**)&h2, g_h2);
    cudaGetSymbolAddress((void**)&h3, g_h3);
    cudaGetSymbolAddress((void**)&z, g_z);
    cudaGetSymbolAddress((void**)&deg, g_deg);
    cudaGetSymbolAddress((void**)&asrc, g_asrc);
    cudaGetSymbolAddress((void**)&atgt, g_atgt);
    cudaGetSymbolAddress((void**)&denom, g_denom);
    cudaGetSymbolAddress((void**)&alpha, g_alpha);
    cudaGetSymbolAddress((void**)&outun, g_outun);
    cudaGetSymbolAddress((void**)&amax, g_amax);

    const int gemmGrid = (NN + 127) / 128;   // 391
    const int scatGrid = (EE + 7) / 8;
    const int fillGrid = 4096;

    // ---- projection: h1 = x @ Wp + bp
    gemm_bf16x3<0, false><<<gemmGrid, 256>>>(x, Wp, nullptr, nullptr, nullptr, bp, h1, NN, DIN, DIN);

    // ---- RGCN layer 1 -> h2
    fill_f4<<<fillGrid, 256>>>((float4*)S, NN * RR * HH / 4, 0.f);
    fill_f4<<<64, 256>>>((float4*)deg, NN * RR / 4, 0.f);
    rgcn_scatter<<<scatGrid, 256>>>(src, tgt, etype, h1, S, deg, EE);
    make_invdeg<<<(NN * RR + 255) / 256, 256>>>(deg, NN * RR);
    gemm_bf16x3<1, true><<<gemmGrid, 256>>>(S, W1, h1, root1, deg, b1, h2, NN, RR * HH + HH, RR * HH);

    // ---- RGCN layer 2 -> h3
    fill_f4<<<fillGrid, 256>>>((float4*)S, NN * RR * HH / 4, 0.f);
    fill_f4<<<64, 256>>>((float4*)deg, NN * RR / 4, 0.f);
    rgcn_scatter<<<scatGrid, 256>>>(src, tgt, etype, h2, S, deg, EE);
    make_invdeg<<<(NN * RR + 255) / 256, 256>>>(deg, NN * RR);
    gemm_bf16x3<1, true><<<gemmGrid, 256>>>(S, W2, h2, root2, deg, b2, h3, NN, RR * HH + HH, RR * HH);

    // ---- GAT
    gemm_bf16x3<0, false><<<gemmGrid, 256>>>(h3, Wg, nullptr, nullptr, nullptr, nullptr, z, NN, HH, HH);
    att_node<<<(NN * HEADS + 255) / 256, 256>>>(z, att, asrc, atgt, NN);
    fill_u4<<<64, 256>>>((uint4*)amax, NN * HEADS / 4, ENC_NEG_INF);
    fill_f4<<<64, 256>>>((float4*)denom, NN * HEADS / 4, 0.f);
    fill_f4<<<512, 256>>>((float4*)outun, NN * HH / 4, 0.f);
    gat_pass1<<<(EE + 255) / 256, 256>>>(src, tgt, asrc, atgt, alpha, amax, EE);
    gat_pass2<<<scatGrid, 256>>>(src, tgt, alpha, amax, z, denom, outun, EE);

    // ---- finalize
    finalize<<<(NN + 7) / 8, 256>>>(outun, denom, bg, Wf, bf, out, NN);
}